// round 8
// baseline (speedup 1.0000x reference)
#include <cuda_runtime.h>
#include <cuda_bf16.h>
#include <stdint.h>
#include <math.h>

#define BB 4
#define NN 1024
#define MM 1024
#define DD 512
#define EPSI 0.1f
#define INV_EPS 10.0f
#define NITER 20
#define ERR_THRESH_TOTAL 0.4f   /* 0.1 * B, since err = total/B */
#define GRID 128
#define NTHR 512

// ---- device scratch (allocation-free: __device__ globals) ----
__device__ __nv_bfloat16 g_Kh[BB*NN*MM];   // exp(-C/eps), bf16
__device__ float g_nx[BB*NN];
__device__ float g_ny[BB*MM];
__device__ float g_u [BB*NN];
__device__ float g_eu[BB*NN];
__device__ float g_ev[BB*MM];
__device__ float g_err[NITER];
__device__ unsigned           g_bar_count = 0;
__device__ volatile unsigned  g_bar_gen   = 0;
__device__ unsigned           g_gc[BB] = {0,0,0,0};
__device__ volatile unsigned  g_gg[BB] = {0,0,0,0};

// ---------------- barriers ----------------
__device__ __forceinline__ void grid_sync() {
    __syncthreads();
    if (threadIdx.x == 0) {
        __threadfence();
        unsigned gen = g_bar_gen;
        if (atomicAdd(&g_bar_count, 1u) == GRID - 1) {
            g_bar_count = 0;
            __threadfence();
            g_bar_gen = gen + 1;
        } else {
            while (g_bar_gen == gen) __nanosleep(32);
        }
    }
    __syncthreads();
}
__device__ __forceinline__ void group_sync(int grp) {
    __syncthreads();
    if (threadIdx.x == 0) {
        __threadfence();
        unsigned gen = g_gg[grp];
        if (atomicAdd(&g_gc[grp], 1u) == (GRID/BB) - 1) {
            g_gc[grp] = 0;
            __threadfence();
            g_gg[grp] = gen + 1;
        } else {
            while (g_gg[grp] == gen) __nanosleep(32);
        }
    }
    __syncthreads();
}

// ---------------------------------------------------------------------------
// tf32 mma.sync GEMM tile: CTA 128x128, 16 warps of 32x32, K chunks of 32,
// double-buffered smem, k-permuted layout -> LDS.64, raw fp32 bits as tf32.
// ---------------------------------------------------------------------------
#define TSTRIDE 36
#define TILE_FLOATS (128*TSTRIDE)

__device__ __forceinline__ void store_perm(uint32_t* dst, int sBase, float4 v) {
    dst[sBase+0] = __float_as_uint(v.x);
    dst[sBase+2] = __float_as_uint(v.y);
    dst[sBase+4] = __float_as_uint(v.z);
    dst[sBase+6] = __float_as_uint(v.w);
}

__device__ void gemm_tile(const float* __restrict__ X, const float* __restrict__ Y,
                          int b, int row0, int col0, float* sm, float* s_ny) {
    const int tid  = threadIdx.x;
    const int lane = tid & 31;
    const int wid  = tid >> 5;
    const int wm   = wid & 3;
    const int wn   = wid >> 2;
    const int g    = lane >> 2;
    const int tig  = lane & 3;

    uint32_t* smA[2] = { (uint32_t*)sm,                 (uint32_t*)(sm + 2*TILE_FLOATS) };
    uint32_t* smB[2] = { (uint32_t*)(sm + TILE_FLOATS), (uint32_t*)(sm + 3*TILE_FLOATS) };

    __syncthreads();
    if (tid < 128) s_ny[tid] = __ldcg(&g_ny[(b << 10) + col0 + tid]);

    const float* Abase = X + ((size_t)b << 19) + ((size_t)row0 << 9);
    const float* Bbase = Y + ((size_t)b << 19) + ((size_t)col0 << 9);
    const float* gA[2]; const float* gB[2];
    int sBase[2];
    #pragma unroll
    for (int q = 0; q < 2; q++) {
        int idx = tid + (q << 9);
        int row = idx >> 3, c4 = idx & 7;
        gA[q] = Abase + ((size_t)row << 9) + (c4 << 2);
        gB[q] = Bbase + ((size_t)row << 9) + (c4 << 2);
        sBase[q] = row * TSTRIDE + ((c4 >> 1) << 3) + (c4 & 1);
    }

    float acc[2][4][4];
    #pragma unroll
    for (int mt = 0; mt < 2; mt++)
        #pragma unroll
        for (int nt = 0; nt < 4; nt++)
            #pragma unroll
            for (int j = 0; j < 4; j++) acc[mt][nt][j] = 0.f;

    #pragma unroll
    for (int q = 0; q < 2; q++) {
        store_perm(smA[0], sBase[q], *(const float4*)(gA[q]));
        store_perm(smB[0], sBase[q], *(const float4*)(gB[q]));
    }
    __syncthreads();

    for (int s = 0; s < 16; s++) {
        const int buf = s & 1;
        float4 pa[2], pb[2];
        if (s < 15) {
            int k0 = (s + 1) << 5;
            #pragma unroll
            for (int q = 0; q < 2; q++) {
                pa[q] = *(const float4*)(gA[q] + k0);
                pb[q] = *(const float4*)(gB[q] + k0);
            }
        }
        #pragma unroll
        for (int k8 = 0; k8 < 4; k8++) {
            uint32_t a[2][4];
            #pragma unroll
            for (int mt = 0; mt < 2; mt++) {
                int r = wm*32 + mt*16 + g;
                uint2 lo = *(uint2*)&smA[buf][r*TSTRIDE     + k8*8 + 2*tig];
                uint2 hi = *(uint2*)&smA[buf][(r+8)*TSTRIDE + k8*8 + 2*tig];
                a[mt][0] = lo.x; a[mt][2] = lo.y;
                a[mt][1] = hi.x; a[mt][3] = hi.y;
            }
            #pragma unroll
            for (int nt = 0; nt < 4; nt++) {
                int c = wn*32 + nt*8 + g;
                uint2 bb = *(uint2*)&smB[buf][c*TSTRIDE + k8*8 + 2*tig];
                #pragma unroll
                for (int mt = 0; mt < 2; mt++) {
                    asm volatile(
                        "mma.sync.aligned.m16n8k8.row.col.f32.tf32.tf32.f32 "
                        "{%0,%1,%2,%3}, {%4,%5,%6,%7}, {%8,%9}, {%0,%1,%2,%3};"
                        : "+f"(acc[mt][nt][0]), "+f"(acc[mt][nt][1]),
                          "+f"(acc[mt][nt][2]), "+f"(acc[mt][nt][3])
                        : "r"(a[mt][0]), "r"(a[mt][1]), "r"(a[mt][2]), "r"(a[mt][3]),
                          "r"(bb.x), "r"(bb.y));
                }
            }
        }
        if (s < 15) {
            const int nb = buf ^ 1;
            #pragma unroll
            for (int q = 0; q < 2; q++) {
                store_perm(smA[nb], sBase[q], pa[q]);
                store_perm(smB[nb], sBase[q], pb[q]);
            }
            __syncthreads();
        }
    }

    // epilogue: K = exp(-(1 - dot/max(nx*ny,1e-8))/eps), stored bf16
    float nxv[2][2];
    #pragma unroll
    for (int mt = 0; mt < 2; mt++) {
        int r = row0 + wm*32 + mt*16 + g;
        nxv[mt][0] = __ldcg(&g_nx[(b << 10) + r]);
        nxv[mt][1] = __ldcg(&g_nx[(b << 10) + r + 8]);
    }
    __nv_bfloat16* Kb = g_Kh + ((size_t)b << 20);
    #pragma unroll
    for (int mt = 0; mt < 2; mt++) {
        #pragma unroll
        for (int nt = 0; nt < 4; nt++) {
            int col = wn*32 + nt*8 + 2*tig;
            float ny0 = s_ny[col], ny1 = s_ny[col + 1];
            int rlo = row0 + wm*32 + mt*16 + g;
            float d0 = fmaxf(nxv[mt][0]*ny0, 1e-8f);
            float d1 = fmaxf(nxv[mt][0]*ny1, 1e-8f);
            float e0 = fmaxf(nxv[mt][1]*ny0, 1e-8f);
            float e1 = fmaxf(nxv[mt][1]*ny1, 1e-8f);
            __nv_bfloat162 vlo = __float22bfloat162_rn(make_float2(
                __expf(-INV_EPS * (1.f - acc[mt][nt][0] / d0)),
                __expf(-INV_EPS * (1.f - acc[mt][nt][1] / d1))));
            __nv_bfloat162 vhi = __float22bfloat162_rn(make_float2(
                __expf(-INV_EPS * (1.f - acc[mt][nt][2] / e0)),
                __expf(-INV_EPS * (1.f - acc[mt][nt][3] / e1))));
            __stcg((unsigned*)(Kb + ((size_t)rlo       << 10) + col0 + col), *(unsigned*)&vlo);
            __stcg((unsigned*)(Kb + ((size_t)(rlo + 8) << 10) + col0 + col), *(unsigned*)&vhi);
        }
    }
}

// ---------------------------------------------------------------------------
__global__ void __launch_bounds__(NTHR, 1)
mega_kernel(const float* __restrict__ x, const float* __restrict__ y,
            const float* __restrict__ nu, float* __restrict__ out) {
    extern __shared__ float sm[];
    __shared__ float s_ny[128];
    __shared__ float2 s_red2[32][17];
    __shared__ float s_err;

    const int tid  = threadIdx.x;
    const int lane = tid & 31;
    const int wid  = tid >> 5;
    const int bid  = blockIdx.x;

    // ---------------- phase 0: init + norms ----------------
    {
        int gtid = bid * NTHR + tid;
        if (gtid < BB*NN) {
            g_u[gtid] = 0.f;
            __stcg(&g_eu[gtid], 1.f);
            __stcg(&g_ev[gtid], 1.f);
        }
        if (gtid < NITER) __stcg(&g_err[gtid], 0.f);
        if (gtid < BB)    __stcg(&out[gtid], 0.f);

        int warpG = bid * 16 + wid;
        #pragma unroll
        for (int q = 0; q < 4; q++) {
            int r = warpG + (q << 11);
            const float4* src = (r < BB*NN)
                ? (const float4*)(x + (size_t)r * DD)
                : (const float4*)(y + (size_t)(r - BB*NN) * DD);
            float s = 0.f;
            #pragma unroll
            for (int i = 0; i < 4; i++) {
                float4 v = __ldg(&src[lane + 32*i]);
                s += v.x*v.x + v.y*v.y + v.z*v.z + v.w*v.w;
            }
            #pragma unroll
            for (int o = 16; o; o >>= 1) s += __shfl_xor_sync(0xffffffffu, s, o);
            if (lane == 0) {
                float nrm = sqrtf(s);
                if (r < BB*NN) __stcg(&g_nx[r], nrm);
                else           __stcg(&g_ny[r - BB*NN], nrm);
            }
        }
    }
    grid_sync();

    // ---------------- phase 1: GEMM (2 tiles per CTA) ----------------
    #pragma unroll
    for (int t2 = 0; t2 < 2; t2++) {
        int t    = bid + (t2 << 7);
        int col0 = (t & 7) << 7;
        int row0 = ((t >> 3) & 7) << 7;
        int b    = t >> 6;
        gemm_tile(x, y, b, row0, col0, sm, s_ny);
    }
    grid_sync();

    // ---------------- phase 2: Sinkhorn iterations ----------------
    const int warpG = bid * 16 + wid;
    const int rbase = warpG << 1;            // 2 rows per warp
    const int grp   = bid >> 5;              // batch group (row & col batch coincide)
    const int j0    = (bid & 31) << 5;       // 32 columns per CTA
    const int c2    = tid & 15;              // column pair
    const int cg    = tid >> 4;              // 0..31 row-group for col pass
    const float LOGMU = logf(1.0f / (float)NN + 1e-8f);
    float2 lognu2 = make_float2(0.f, 0.f);
    if (tid < 16) {
        lognu2.x = __logf(__ldg(&nu[(grp << 10) + j0 + 2*c2])     + 1e-8f);
        lognu2.y = __logf(__ldg(&nu[(grp << 10) + j0 + 2*c2 + 1]) + 1e-8f);
    }
    float* s_eu = sm;                        // 1024 floats

    for (int it = 0; it < NITER; it++) {
        if (tid == 0) s_err = 0.f;
        __syncthreads();

        // ---- row pass: u update ----
        {
            const float4* evp = (const float4*)(g_ev + (grp << 10));
            float4 ev4[8];
            #pragma unroll
            for (int i = 0; i < 4; i++) {
                ev4[2*i]   = __ldcg(&evp[2*(lane + 32*i)]);
                ev4[2*i+1] = __ldcg(&evp[2*(lane + 32*i) + 1]);
            }
            float myerr = 0.f;
            #pragma unroll
            for (int rr = 0; rr < 2; rr++) {
                int r = rbase + rr;
                const uint4* Kp = (const uint4*)(g_Kh + ((size_t)r << 10));
                float s = 0.f;
                #pragma unroll
                for (int i = 0; i < 4; i++) {
                    uint4 kq = __ldg(&Kp[lane + 32*i]);
                    float2 f0 = __bfloat1622float2(*(__nv_bfloat162*)&kq.x);
                    float2 f1 = __bfloat1622float2(*(__nv_bfloat162*)&kq.y);
                    float2 f2 = __bfloat1622float2(*(__nv_bfloat162*)&kq.z);
                    float2 f3 = __bfloat1622float2(*(__nv_bfloat162*)&kq.w);
                    s += f0.x*ev4[2*i].x + f0.y*ev4[2*i].y
                       + f1.x*ev4[2*i].z + f1.y*ev4[2*i].w
                       + f2.x*ev4[2*i+1].x + f2.y*ev4[2*i+1].y
                       + f3.x*ev4[2*i+1].z + f3.y*ev4[2*i+1].w;
                }
                #pragma unroll
                for (int o = 16; o; o >>= 1) s += __shfl_xor_sync(0xffffffffu, s, o);
                if (lane == 0) {
                    float u_old = g_u[r];
                    float u_new = EPSI * LOGMU - EPSI * __logf(s);
                    myerr += fabsf(u_new - u_old);
                    g_u[r] = u_new;
                    __stcg(&g_eu[r], __expf(u_new * INV_EPS));
                }
            }
            if (lane == 0) atomicAdd(&s_err, myerr);
        }
        __syncthreads();
        if (tid == 0) atomicAdd(&g_err[it], s_err);
        group_sync(grp);                      // eu for this batch ready

        // ---- col pass: v update ----
        {
            if (tid < 256) ((float4*)s_eu)[tid] = __ldcg((const float4*)(g_eu + (grp << 10)) + tid);
            __syncthreads();
            const __nv_bfloat162* Kb = (const __nv_bfloat162*)(g_Kh + ((size_t)grp << 20) + j0);
            float2 s = make_float2(0.f, 0.f);
            #pragma unroll 8
            for (int i = cg; i < NN; i += 32) {
                float2 k = __bfloat1622float2(__ldg(&Kb[(i << 9) + c2]));
                float e = s_eu[i];
                s.x += k.x * e;  s.y += k.y * e;
            }
            s_red2[cg][c2] = s;
            __syncthreads();
            if (tid < 16) {
                float2 tot = make_float2(0.f, 0.f);
                #pragma unroll
                for (int q = 0; q < 32; q++) { tot.x += s_red2[q][c2].x; tot.y += s_red2[q][c2].y; }
                float2 vn;
                vn.x = __expf((EPSI * lognu2.x - EPSI * __logf(tot.x)) * INV_EPS);
                vn.y = __expf((EPSI * lognu2.y - EPSI * __logf(tot.y)) * INV_EPS);
                __stcg((float2*)(g_ev + (grp << 10) + j0 + 2*c2), vn);
            }
        }
        grid_sync();                          // ev ready + err[it] visible grid-wide
        if (__ldcg(&g_err[it]) < ERR_THRESH_TOTAL) break;
    }

    // ---------------- phase 3: cost = sum_ij (-eps lnK) K eu ev ----------------
    {
        __syncthreads();
        if (tid < 256) ((float4*)s_eu)[tid] = __ldcg((const float4*)(g_eu + (grp << 10)) + tid);
        __syncthreads();
        const __nv_bfloat162* Kb = (const __nv_bfloat162*)(g_Kh + ((size_t)grp << 20) + j0);
        float2 s = make_float2(0.f, 0.f);
        #pragma unroll 8
        for (int i = cg; i < NN; i += 32) {
            float2 k = __bfloat1622float2(__ldg(&Kb[(i << 9) + c2]));
            float e = s_eu[i];
            s.x += k.x * __logf(k.x) * e;
            s.y += k.y * __logf(k.y) * e;
        }
        s_red2[cg][c2] = s;
        __syncthreads();
        if (tid < 16) {
            float2 tot = make_float2(0.f, 0.f);
            #pragma unroll
            for (int q = 0; q < 32; q++) { tot.x += s_red2[q][c2].x; tot.y += s_red2[q][c2].y; }
            float ev0 = __ldcg(&g_ev[(grp << 10) + j0 + 2*c2]);
            float ev1 = __ldcg(&g_ev[(grp << 10) + j0 + 2*c2 + 1]);
            float contrib = -EPSI * (tot.x * ev0 + tot.y * ev1);
            #pragma unroll
            for (int o = 8; o; o >>= 1) contrib += __shfl_xor_sync(0x0000ffffu, contrib, o);
            if (c2 == 0) atomicAdd(out + grp, contrib);
        }
    }
}

// ---------------------------------------------------------------------------
extern "C" void kernel_launch(void* const* d_in, const int* in_sizes, int n_in,
                              void* d_out, int out_size) {
    const float* x  = (const float*)d_in[0];   // [B,N,D]
    const float* y  = (const float*)d_in[1];   // [B,M,D]
    const float* nu = (const float*)d_in[2];   // [B,M]
    float* out = (float*)d_out;                // [B]

    const int dyn = 4 * TILE_FLOATS * 4;       // 73728 bytes
    cudaFuncSetAttribute(mega_kernel, cudaFuncAttributeMaxDynamicSharedMemorySize, dyn);
    mega_kernel<<<GRID, NTHR, dyn>>>(x, y, nu, out);
}

// round 10
// speedup vs baseline: 1.7439x; 1.7439x over previous
#include <cuda_runtime.h>
#include <stdint.h>
#include <math.h>

#define BB 4
#define NN 1024
#define MM 1024
#define DD 512
#define EPSI 0.1f
#define INV_EPS 10.0f
#define NITER 20
#define ERR_THRESH_TOTAL 0.4f   /* 0.1 * B, since err = total/B */
#define GRID 128
#define NTHR 512

// ---- device scratch (allocation-free: __device__ globals) ----
__device__ float g_K[BB*NN*MM];   // exp(-C/eps)
__device__ float g_nx[BB*NN];
__device__ float g_ny[BB*MM];
__device__ float g_u [BB*NN];
__device__ float g_eu[BB*NN];
__device__ float g_ev[BB*MM];
__device__ float g_err[NITER];
__device__ unsigned           g_bar_count = 0;
__device__ volatile unsigned  g_bar_gen   = 0;
__device__ unsigned           g_gc[BB] = {0,0,0,0};
__device__ volatile unsigned  g_gg[BB] = {0,0,0,0};

// ---------------- barriers ----------------
__device__ __forceinline__ void grid_sync() {
    __syncthreads();
    if (threadIdx.x == 0) {
        __threadfence();
        unsigned gen = g_bar_gen;
        if (atomicAdd(&g_bar_count, 1u) == GRID - 1) {
            g_bar_count = 0;
            __threadfence();
            g_bar_gen = gen + 1;
        } else {
            while (g_bar_gen == gen) __nanosleep(32);
        }
    }
    __syncthreads();
}
__device__ __forceinline__ void group_sync(int grp) {
    __syncthreads();
    if (threadIdx.x == 0) {
        __threadfence();
        unsigned gen = g_gg[grp];
        if (atomicAdd(&g_gc[grp], 1u) == (GRID/BB) - 1) {
            g_gc[grp] = 0;
            __threadfence();
            g_gg[grp] = gen + 1;
        } else {
            while (g_gg[grp] == gen) __nanosleep(32);
        }
    }
    __syncthreads();
}

// ---------------------------------------------------------------------------
// tf32 mma.sync GEMM tile: CTA 128x128, 16 warps of 32x32, K chunks of 32,
// double-buffered smem, k-permuted layout -> LDS.64, raw fp32 bits as tf32.
// ---------------------------------------------------------------------------
#define TSTRIDE 36
#define TILE_FLOATS (128*TSTRIDE)

__device__ __forceinline__ void store_perm(uint32_t* dst, int sBase, float4 v) {
    dst[sBase+0] = __float_as_uint(v.x);
    dst[sBase+2] = __float_as_uint(v.y);
    dst[sBase+4] = __float_as_uint(v.z);
    dst[sBase+6] = __float_as_uint(v.w);
}

__device__ void gemm_tile(const float* __restrict__ X, const float* __restrict__ Y,
                          int b, int row0, int col0, float* sm, float* s_ny) {
    const int tid  = threadIdx.x;
    const int lane = tid & 31;
    const int wid  = tid >> 5;
    const int wm   = wid & 3;
    const int wn   = wid >> 2;
    const int g    = lane >> 2;
    const int tig  = lane & 3;

    uint32_t* smA[2] = { (uint32_t*)sm,                 (uint32_t*)(sm + 2*TILE_FLOATS) };
    uint32_t* smB[2] = { (uint32_t*)(sm + TILE_FLOATS), (uint32_t*)(sm + 3*TILE_FLOATS) };

    __syncthreads();
    if (tid < 128) s_ny[tid] = __ldcg(&g_ny[(b << 10) + col0 + tid]);

    const float* Abase = X + ((size_t)b << 19) + ((size_t)row0 << 9);
    const float* Bbase = Y + ((size_t)b << 19) + ((size_t)col0 << 9);
    const float* gA[2]; const float* gB[2];
    int sBase[2];
    #pragma unroll
    for (int q = 0; q < 2; q++) {
        int idx = tid + (q << 9);
        int row = idx >> 3, c4 = idx & 7;
        gA[q] = Abase + ((size_t)row << 9) + (c4 << 2);
        gB[q] = Bbase + ((size_t)row << 9) + (c4 << 2);
        sBase[q] = row * TSTRIDE + ((c4 >> 1) << 3) + (c4 & 1);
    }

    float acc[2][4][4];
    #pragma unroll
    for (int mt = 0; mt < 2; mt++)
        #pragma unroll
        for (int nt = 0; nt < 4; nt++)
            #pragma unroll
            for (int j = 0; j < 4; j++) acc[mt][nt][j] = 0.f;

    #pragma unroll
    for (int q = 0; q < 2; q++) {
        store_perm(smA[0], sBase[q], *(const float4*)(gA[q]));
        store_perm(smB[0], sBase[q], *(const float4*)(gB[q]));
    }
    __syncthreads();

    for (int s = 0; s < 16; s++) {
        const int buf = s & 1;
        float4 pa[2], pb[2];
        if (s < 15) {
            int k0 = (s + 1) << 5;
            #pragma unroll
            for (int q = 0; q < 2; q++) {
                pa[q] = *(const float4*)(gA[q] + k0);
                pb[q] = *(const float4*)(gB[q] + k0);
            }
        }
        #pragma unroll
        for (int k8 = 0; k8 < 4; k8++) {
            uint32_t a[2][4];
            #pragma unroll
            for (int mt = 0; mt < 2; mt++) {
                int r = wm*32 + mt*16 + g;
                uint2 lo = *(uint2*)&smA[buf][r*TSTRIDE     + k8*8 + 2*tig];
                uint2 hi = *(uint2*)&smA[buf][(r+8)*TSTRIDE + k8*8 + 2*tig];
                a[mt][0] = lo.x; a[mt][2] = lo.y;
                a[mt][1] = hi.x; a[mt][3] = hi.y;
            }
            #pragma unroll
            for (int nt = 0; nt < 4; nt++) {
                int c = wn*32 + nt*8 + g;
                uint2 bb = *(uint2*)&smB[buf][c*TSTRIDE + k8*8 + 2*tig];
                #pragma unroll
                for (int mt = 0; mt < 2; mt++) {
                    asm volatile(
                        "mma.sync.aligned.m16n8k8.row.col.f32.tf32.tf32.f32 "
                        "{%0,%1,%2,%3}, {%4,%5,%6,%7}, {%8,%9}, {%0,%1,%2,%3};"
                        : "+f"(acc[mt][nt][0]), "+f"(acc[mt][nt][1]),
                          "+f"(acc[mt][nt][2]), "+f"(acc[mt][nt][3])
                        : "r"(a[mt][0]), "r"(a[mt][1]), "r"(a[mt][2]), "r"(a[mt][3]),
                          "r"(bb.x), "r"(bb.y));
                }
            }
        }
        if (s < 15) {
            const int nb = buf ^ 1;
            #pragma unroll
            for (int q = 0; q < 2; q++) {
                store_perm(smA[nb], sBase[q], pa[q]);
                store_perm(smB[nb], sBase[q], pb[q]);
            }
            __syncthreads();
        }
    }

    // epilogue: K = exp(-(1 - dot/max(nx*ny,1e-8))/eps)
    float nxv[2][2];
    #pragma unroll
    for (int mt = 0; mt < 2; mt++) {
        int r = row0 + wm*32 + mt*16 + g;
        nxv[mt][0] = __ldcg(&g_nx[(b << 10) + r]);
        nxv[mt][1] = __ldcg(&g_nx[(b << 10) + r + 8]);
    }
    float* Kb = g_K + ((size_t)b << 20);
    #pragma unroll
    for (int mt = 0; mt < 2; mt++) {
        #pragma unroll
        for (int nt = 0; nt < 4; nt++) {
            int col = wn*32 + nt*8 + 2*tig;
            float ny0 = s_ny[col], ny1 = s_ny[col + 1];
            int rlo = row0 + wm*32 + mt*16 + g;
            float2 vlo, vhi;
            float d0 = fmaxf(nxv[mt][0]*ny0, 1e-8f);
            float d1 = fmaxf(nxv[mt][0]*ny1, 1e-8f);
            vlo.x = __expf(-INV_EPS * (1.f - acc[mt][nt][0] / d0));
            vlo.y = __expf(-INV_EPS * (1.f - acc[mt][nt][1] / d1));
            float e0 = fmaxf(nxv[mt][1]*ny0, 1e-8f);
            float e1 = fmaxf(nxv[mt][1]*ny1, 1e-8f);
            vhi.x = __expf(-INV_EPS * (1.f - acc[mt][nt][2] / e0));
            vhi.y = __expf(-INV_EPS * (1.f - acc[mt][nt][3] / e1));
            __stcg((float2*)(Kb + ((size_t)rlo       << 10) + col0 + col), vlo);
            __stcg((float2*)(Kb + ((size_t)(rlo + 8) << 10) + col0 + col), vhi);
        }
    }
}

// ---------------------------------------------------------------------------
__global__ void __launch_bounds__(NTHR, 1)
mega_kernel(const float* __restrict__ x, const float* __restrict__ y,
            const float* __restrict__ nu, float* __restrict__ out) {
    extern __shared__ float sm[];
    __shared__ float s_ny[128];
    __shared__ float s_red[16][33];
    __shared__ float s_err;

    const int tid  = threadIdx.x;
    const int lane = tid & 31;
    const int wid  = tid >> 5;
    const int bid  = blockIdx.x;

    // ---------------- phase 0: init + norms ----------------
    {
        int gtid = bid * NTHR + tid;
        if (gtid < BB*NN) {
            g_u[gtid] = 0.f;
            __stcg(&g_eu[gtid], 1.f);
            __stcg(&g_ev[gtid], 1.f);
        }
        if (gtid < NITER) __stcg(&g_err[gtid], 0.f);
        if (gtid < BB)    __stcg(&out[gtid], 0.f);

        int warpG = bid * 16 + wid;
        #pragma unroll
        for (int q = 0; q < 4; q++) {
            int r = warpG + (q << 11);
            const float4* src = (r < BB*NN)
                ? (const float4*)(x + (size_t)r * DD)
                : (const float4*)(y + (size_t)(r - BB*NN) * DD);
            float s = 0.f;
            #pragma unroll
            for (int i = 0; i < 4; i++) {
                float4 v = __ldg(&src[lane + 32*i]);
                s += v.x*v.x + v.y*v.y + v.z*v.z + v.w*v.w;
            }
            #pragma unroll
            for (int o = 16; o; o >>= 1) s += __shfl_xor_sync(0xffffffffu, s, o);
            if (lane == 0) {
                float nrm = sqrtf(s);
                if (r < BB*NN) __stcg(&g_nx[r], nrm);
                else           __stcg(&g_ny[r - BB*NN], nrm);
            }
        }
    }
    grid_sync();

    // ---------------- phase 1: GEMM (2 tiles per CTA) ----------------
    #pragma unroll
    for (int t2 = 0; t2 < 2; t2++) {
        int t    = bid + (t2 << 7);
        int col0 = (t & 7) << 7;
        int row0 = ((t >> 3) & 7) << 7;
        int b    = t >> 6;
        gemm_tile(x, y, b, row0, col0, sm, s_ny);
    }
    grid_sync();

    // ---------------- phase 2: Sinkhorn iterations ----------------
    const int warpG = bid * 16 + wid;
    const int rbase = warpG << 1;            // 2 rows per warp
    const int grp   = bid >> 5;              // batch (rows & cols coincide)
    const int j0    = (bid & 31) << 5;       // 32 columns per CTA
    const float LOGMU = logf(1.0f / (float)NN + 1e-8f);
    float lognu = 0.f;
    if (tid < 32) lognu = __logf(__ldg(&nu[(grp << 10) + j0 + tid]) + 1e-8f);
    float* s_eu = sm;                        // 1024 floats

    for (int it = 0; it < NITER; it++) {
        if (tid == 0) s_err = 0.f;
        __syncthreads();

        // ---- row pass: u update (2 rows interleaved, 24 loads in flight) ----
        {
            const float4* evp = (const float4*)(g_ev + (grp << 10));
            const float4* Kp0 = (const float4*)(g_K + ((size_t)rbase << 10));
            const float4* Kp1 = (const float4*)(g_K + ((size_t)(rbase + 1) << 10));
            float4 evr[8], k0[8], k1[8];
            #pragma unroll
            for (int i = 0; i < 8; i++) evr[i] = __ldg(&evp[lane + 32*i]);
            #pragma unroll
            for (int i = 0; i < 8; i++) k0[i] = __ldg(&Kp0[lane + 32*i]);
            #pragma unroll
            for (int i = 0; i < 8; i++) k1[i] = __ldg(&Kp1[lane + 32*i]);
            float s0 = 0.f, s1 = 0.f;
            #pragma unroll
            for (int i = 0; i < 8; i++) {
                s0 += k0[i].x*evr[i].x + k0[i].y*evr[i].y + k0[i].z*evr[i].z + k0[i].w*evr[i].w;
                s1 += k1[i].x*evr[i].x + k1[i].y*evr[i].y + k1[i].z*evr[i].z + k1[i].w*evr[i].w;
            }
            #pragma unroll
            for (int o = 16; o; o >>= 1) {
                s0 += __shfl_xor_sync(0xffffffffu, s0, o);
                s1 += __shfl_xor_sync(0xffffffffu, s1, o);
            }
            if (lane == 0) {
                float u0 = EPSI * LOGMU - EPSI * __logf(s0);
                float u1 = EPSI * LOGMU - EPSI * __logf(s1);
                float myerr = fabsf(u0 - g_u[rbase]) + fabsf(u1 - g_u[rbase + 1]);
                g_u[rbase]     = u0;
                g_u[rbase + 1] = u1;
                __stcg(&g_eu[rbase],     __expf(u0 * INV_EPS));
                __stcg(&g_eu[rbase + 1], __expf(u1 * INV_EPS));
                atomicAdd(&s_err, myerr);
            }
        }
        __syncthreads();
        if (tid == 0) atomicAdd(&g_err[it], s_err);
        group_sync(grp);                      // eu for this batch ready

        // ---- col pass: v update ----
        {
            if (tid < 256) ((float4*)s_eu)[tid] = __ldcg((const float4*)(g_eu + (grp << 10)) + tid);
            __syncthreads();
            const int c = tid & 31, g = tid >> 5;     // g = 0..15
            const float* Kb = g_K + ((size_t)grp << 20) + j0 + c;
            float s = 0.f;
            #pragma unroll 16
            for (int i = g; i < NN; i += 16)
                s += __ldg(&Kb[(size_t)i << 10]) * s_eu[i];
            s_red[g][c] = s;
            __syncthreads();
            if (g == 0) {
                float tot = 0.f;
                #pragma unroll
                for (int q = 0; q < 16; q++) tot += s_red[q][c];
                float v_new = EPSI * lognu - EPSI * __logf(tot);
                __stcg(&g_ev[(grp << 10) + j0 + c], __expf(v_new * INV_EPS));
            }
        }
        grid_sync();                          // ev ready + err[it] visible grid-wide
        if (__ldcg(&g_err[it]) < ERR_THRESH_TOTAL) break;
    }

    // ---------------- phase 3: cost = sum_ij (-eps lnK) K eu ev ----------------
    {
        __syncthreads();
        if (tid < 256) ((float4*)s_eu)[tid] = __ldcg((const float4*)(g_eu + (grp << 10)) + tid);
        __syncthreads();
        const int c = tid & 31, g = tid >> 5;
        const float* Kb = g_K + ((size_t)grp << 20) + j0 + c;
        float s = 0.f;
        #pragma unroll 16
        for (int i = g; i < NN; i += 16) {
            float kv = __ldg(&Kb[(size_t)i << 10]);
            s += kv * __logf(kv) * s_eu[i];
        }
        s_red[g][c] = s;
        __syncthreads();
        if (g == 0) {
            float tot = 0.f;
            #pragma unroll
            for (int q = 0; q < 16; q++) tot += s_red[q][c];
            float evj = __ldcg(&g_ev[(grp << 10) + j0 + c]);
            float contrib = -EPSI * tot * evj;
            #pragma unroll
            for (int o = 16; o; o >>= 1) contrib += __shfl_xor_sync(0xffffffffu, contrib, o);
            if (c == 0) atomicAdd(out + grp, contrib);
        }
    }
}

// ---------------------------------------------------------------------------
extern "C" void kernel_launch(void* const* d_in, const int* in_sizes, int n_in,
                              void* d_out, int out_size) {
    const float* x  = (const float*)d_in[0];   // [B,N,D]
    const float* y  = (const float*)d_in[1];   // [B,M,D]
    const float* nu = (const float*)d_in[2];   // [B,M]
    float* out = (float*)d_out;                // [B]

    const int dyn = 4 * TILE_FLOATS * 4;       // 73728 bytes
    cudaFuncSetAttribute(mega_kernel, cudaFuncAttributeMaxDynamicSharedMemorySize, dyn);
    mega_kernel<<<GRID, NTHR, dyn>>>(x, y, nu, out);
}